// round 8
// baseline (speedup 1.0000x reference)
#include <cuda_runtime.h>
#include <math.h>

// ---------------------------------------------------------------------------
// Problem constants
// ---------------------------------------------------------------------------
constexpr int B_  = 32;
constexpr int L_  = 256;
constexpr int D_  = 256;
constexpr int E_  = 32;
constexpr int H_  = 8;
constexpr int HD_ = 32;
constexpr float SCALE_ = 0.17677669529663687f;  // 1/sqrt(32)

constexpr int ROWS_ = B_ * L_;   // 8192

// ---------------------------------------------------------------------------
// Device scratch
// ---------------------------------------------------------------------------
__device__ float g_qkv[ROWS_ * 3 * D_];   // [B*L, 768]  q|k|v
__device__ float g_aout[ROWS_ * D_];      // [B*L, 256]

// ---------------------------------------------------------------------------
// helpers
// ---------------------------------------------------------------------------
using u64 = unsigned long long;

__device__ __forceinline__ unsigned s2u(const void* p) {
    return (unsigned)__cvta_generic_to_shared(p);
}
__device__ __forceinline__ u64 fma2(u64 a, u64 b, u64 c) {
    u64 d; asm("fma.rn.f32x2 %0, %1, %2, %3;" : "=l"(d) : "l"(a), "l"(b), "l"(c));
    return d;
}
__device__ __forceinline__ u64 mul2(u64 a, u64 b) {
    u64 d; asm("mul.rn.f32x2 %0, %1, %2;" : "=l"(d) : "l"(a), "l"(b));
    return d;
}
__device__ __forceinline__ float hsum2(u64 a) {
    float lo, hi;
    asm("mov.b64 {%0,%1}, %2;" : "=f"(lo), "=f"(hi) : "l"(a));
    return lo + hi;
}
__device__ __forceinline__ u64 dup2(float x) {
    u64 d; asm("mov.b64 %0, {%1,%1};" : "=l"(d) : "f"(x)); return d;
}
__device__ __forceinline__ u64 pk2(float x, float y) {
    u64 d; asm("mov.b64 %0, {%1,%2};" : "=l"(d) : "f"(x), "f"(y)); return d;
}
__device__ __forceinline__ void cp_async16(unsigned smem_dst, const void* gmem_src) {
    asm volatile("cp.async.cg.shared.global [%0], [%1], 16;\n"
                 :: "r"(smem_dst), "l"(gmem_src) : "memory");
}
__device__ __forceinline__ void cp_commit() {
    asm volatile("cp.async.commit_group;\n" ::: "memory");
}
__device__ __forceinline__ void cp_wait0() {
    asm volatile("cp.async.wait_group 0;\n" ::: "memory");
}
// tf32 conversion + split (3xTF32)
__device__ __forceinline__ unsigned f2tf(float x) {
    unsigned r; asm("cvt.rna.tf32.f32 %0, %1;" : "=r"(r) : "f"(x)); return r;
}
__device__ __forceinline__ void tfsplit(float x, unsigned& hi, unsigned& lo) {
    hi = f2tf(x);
    lo = f2tf(x - __uint_as_float(hi));
}
// m16n8k8 tf32 MMA, D += A*B
__device__ __forceinline__ void mma8(float* d, const unsigned* a, const unsigned* b) {
    asm volatile(
        "mma.sync.aligned.m16n8k8.row.col.f32.tf32.tf32.f32 "
        "{%0,%1,%2,%3},{%4,%5,%6,%7},{%8,%9},{%0,%1,%2,%3};"
        : "+f"(d[0]), "+f"(d[1]), "+f"(d[2]), "+f"(d[3])
        : "r"(a[0]), "r"(a[1]), "r"(a[2]), "r"(a[3]), "r"(b[0]), "r"(b[1]));
}
__device__ __forceinline__ void mma3x(float* d, const unsigned* ah, const unsigned* al,
                                      const unsigned* bh, const unsigned* bl) {
    mma8(d, ah, bh);
    mma8(d, ah, bl);
    mma8(d, al, bh);
}

// ---------------------------------------------------------------------------
// Kernel 1/3: tf32 tensor-core GEMM, C = A @ W^T + bias (3xTF32)
// Pre-split hi/lo planes in smem; register prefetch of next tile.
// BM=128, BN=64, BK=32, 256 threads, warp grid 4m x 2n, warp tile 32x32.
// ---------------------------------------------------------------------------
constexpr int GBM = 128;
constexpr int GBN = 64;
constexpr int GBK = 32;
constexpr int GSTR = GBK + 4;    // 36: bank = (4*row + col) % 32 -> conflict-free

struct GemmSmem {
    float Ah[GBM][GSTR];
    float Al[GBM][GSTR];
    float Wh[GBN][GSTR];
    float Wl[GBN][GSTR];
};

__global__ __launch_bounds__(256, 2)
void tf32_gemm_nt_bias(const float* __restrict__ A, const float* __restrict__ W,
                       const float* __restrict__ bias, float* __restrict__ C,
                       int M, int N, int K)
{
    extern __shared__ char smem_raw[];
    GemmSmem& sm = *reinterpret_cast<GemmSmem*>(smem_raw);

    const int tid  = threadIdx.x;
    const int w    = tid >> 5;
    const int lane = tid & 31;
    const int gid  = lane >> 2;
    const int ctg  = lane & 3;
    const int wm   = w >> 1;        // 0..3
    const int wn   = w & 1;         // 0..1
    const int m0   = blockIdx.y * GBM;
    const int n0   = blockIdx.x * GBN;

    const int NIT = K / GBK;

    // per-thread staging slots
    int arow[4], ac4[4], wrow[2], wc4[2];
#pragma unroll
    for (int it = 0; it < 4; ++it) {
        int idx = tid + it * 256;          // 0..1023
        arow[it] = idx >> 3;
        ac4[it]  = (idx & 7) * 4;
    }
#pragma unroll
    for (int it = 0; it < 2; ++it) {
        int idx = tid + it * 256;          // 0..511
        wrow[it] = idx >> 3;
        wc4[it]  = (idx & 7) * 4;
    }

    // --- prologue: LDG tile 0 into registers ---
    float4 ar[4], wr[2];
#pragma unroll
    for (int it = 0; it < 4; ++it)
        ar[it] = *(const float4*)&A[(size_t)(m0 + arow[it]) * K + ac4[it]];
#pragma unroll
    for (int it = 0; it < 2; ++it)
        wr[it] = *(const float4*)&W[(size_t)(n0 + wrow[it]) * K + wc4[it]];

    float acc[2][4][4];
#pragma unroll
    for (int mt = 0; mt < 2; mt++)
#pragma unroll
        for (int nt = 0; nt < 4; nt++)
#pragma unroll
            for (int e = 0; e < 4; e++) acc[mt][nt][e] = 0.f;

    for (int i = 0; i < NIT; i++) {
        __syncthreads();   // previous compute done reading smem

        // split (once per element) + store both planes
#pragma unroll
        for (int it = 0; it < 4; ++it) {
            unsigned h0,l0,h1,l1,h2,l2,h3,l3;
            tfsplit(ar[it].x, h0, l0); tfsplit(ar[it].y, h1, l1);
            tfsplit(ar[it].z, h2, l2); tfsplit(ar[it].w, h3, l3);
            float4 hv = make_float4(__uint_as_float(h0), __uint_as_float(h1),
                                    __uint_as_float(h2), __uint_as_float(h3));
            float4 lv = make_float4(__uint_as_float(l0), __uint_as_float(l1),
                                    __uint_as_float(l2), __uint_as_float(l3));
            *(float4*)&sm.Ah[arow[it]][ac4[it]] = hv;
            *(float4*)&sm.Al[arow[it]][ac4[it]] = lv;
        }
#pragma unroll
        for (int it = 0; it < 2; ++it) {
            unsigned h0,l0,h1,l1,h2,l2,h3,l3;
            tfsplit(wr[it].x, h0, l0); tfsplit(wr[it].y, h1, l1);
            tfsplit(wr[it].z, h2, l2); tfsplit(wr[it].w, h3, l3);
            float4 hv = make_float4(__uint_as_float(h0), __uint_as_float(h1),
                                    __uint_as_float(h2), __uint_as_float(h3));
            float4 lv = make_float4(__uint_as_float(l0), __uint_as_float(l1),
                                    __uint_as_float(l2), __uint_as_float(l3));
            *(float4*)&sm.Wh[wrow[it]][wc4[it]] = hv;
            *(float4*)&sm.Wl[wrow[it]][wc4[it]] = lv;
        }
        __syncthreads();   // planes visible

        // prefetch tile i+1 (LDG latency hidden under compute)
        if (i + 1 < NIT) {
            const int k0 = (i + 1) * GBK;
#pragma unroll
            for (int it = 0; it < 4; ++it)
                ar[it] = *(const float4*)&A[(size_t)(m0 + arow[it]) * K + k0 + ac4[it]];
#pragma unroll
            for (int it = 0; it < 2; ++it)
                wr[it] = *(const float4*)&W[(size_t)(n0 + wrow[it]) * K + k0 + wc4[it]];
        }

        // compute: pure LDS + MMA
#pragma unroll
        for (int ks = 0; ks < 4; ks++) {
            const int kc = ks * 8 + ctg;
            unsigned ah[2][4], al[2][4];
#pragma unroll
            for (int mt = 0; mt < 2; mt++) {
                const int r0 = wm * 32 + mt * 16 + gid;
                ah[mt][0] = __float_as_uint(sm.Ah[r0][kc]);
                ah[mt][1] = __float_as_uint(sm.Ah[r0 + 8][kc]);
                ah[mt][2] = __float_as_uint(sm.Ah[r0][kc + 4]);
                ah[mt][3] = __float_as_uint(sm.Ah[r0 + 8][kc + 4]);
                al[mt][0] = __float_as_uint(sm.Al[r0][kc]);
                al[mt][1] = __float_as_uint(sm.Al[r0 + 8][kc]);
                al[mt][2] = __float_as_uint(sm.Al[r0][kc + 4]);
                al[mt][3] = __float_as_uint(sm.Al[r0 + 8][kc + 4]);
            }
#pragma unroll
            for (int nt = 0; nt < 4; nt++) {
                const int nr = wn * 32 + nt * 8 + gid;
                unsigned bh[2], bl[2];
                bh[0] = __float_as_uint(sm.Wh[nr][kc]);
                bh[1] = __float_as_uint(sm.Wh[nr][kc + 4]);
                bl[0] = __float_as_uint(sm.Wl[nr][kc]);
                bl[1] = __float_as_uint(sm.Wl[nr][kc + 4]);
                mma3x(acc[0][nt], ah[0], al[0], bh, bl);
                mma3x(acc[1][nt], ah[1], al[1], bh, bl);
            }
        }
    }

    // --- epilogue: + bias, u64 paired stores ---
#pragma unroll
    for (int mt = 0; mt < 2; mt++) {
        const int row = m0 + wm * 32 + mt * 16 + gid;
#pragma unroll
        for (int nt = 0; nt < 4; nt++) {
            const int col = n0 + wn * 32 + nt * 8 + 2 * ctg;
            const float b0 = bias[col], b1 = bias[col + 1];
            *(u64*)&C[(size_t)row * N + col] =
                pk2(acc[mt][nt][0] + b0, acc[mt][nt][1] + b1);
            *(u64*)&C[(size_t)(row + 8) * N + col] =
                pk2(acc[mt][nt][2] + b0, acc[mt][nt][3] + b1);
        }
    }
}

// ---------------------------------------------------------------------------
// Kernel 2: fused edge attention (v7 — b3/eob hoisted; otherwise r6)
// ---------------------------------------------------------------------------
constexpr int QT = 16;
constexpr int KT = 16;
constexpr int NT = L_ / KT;        // 16 k-tiles
constexpr int QSTR  = D_ + 4;      // 260
constexpr int SROWQ = 20;          // words per q-row in s/g
constexpr int SROWH = QT * SROWQ + 4;  // 324 words per head

struct AttnSmem {
    float q[QT][QSTR];
    float k[KT][QSTR];
    float ex[QT * KT][E_];        // XOR-swizzled at float4 granularity
    float s[H_ * SROWH];
    float g[H_ * SROWH];
    float m[H_][QT];
    float z[H_][QT];
    float r[H_][QT];
    float w2hi[16][36];
    float w2lo[16][36];
    float eowhi[E_][9];
    float eowlo[E_][9];
    float eb[H_];
    float gb[H_];
    float eob[E_];
};

__device__ __forceinline__ int ex_idx(int row, int col) {
    return row * 32 + (((col >> 2) ^ (row & 7)) << 2) + (col & 3);
}

__global__ __launch_bounds__(256, 2)
void edge_attn_kernel(const float* __restrict__ edge_x,
                      const float* __restrict__ e_w, const float* __restrict__ e_b,
                      const float* __restrict__ g_w, const float* __restrict__ g_b,
                      const float* __restrict__ eo_w, const float* __restrict__ eo_b,
                      float* __restrict__ edge_out)
{
    extern __shared__ char smem_raw[];
    AttnSmem& sm = *reinterpret_cast<AttnSmem*>(smem_raw);

    const int tid = threadIdx.x;
    const int b   = blockIdx.y;
    const int q0  = blockIdx.x * QT;
    const size_t bL = (size_t)b * L_;

    const int w    = tid >> 5;
    const int lane = tid & 31;
    const int gid  = lane >> 2;
    const int ctg  = lane & 3;

#pragma unroll
    for (int it = 0; it < 2; ++it) {
        int idx = tid + it * 256;
        int rr = idx >> 5, cc = idx & 31;
        float val = (rr < 8) ? e_w[rr * E_ + cc] : g_w[(rr - 8) * E_ + cc];
        unsigned hi, lo; tfsplit(val, hi, lo);
        sm.w2hi[rr][cc] = __uint_as_float(hi);
        sm.w2lo[rr][cc] = __uint_as_float(lo);
    }
    {
        int n = tid >> 3, hc = tid & 7;
        unsigned hi, lo; tfsplit(eo_w[n * H_ + hc], hi, lo);
        sm.eowhi[n][hc] = __uint_as_float(hi);
        sm.eowlo[n][hc] = __uint_as_float(lo);
    }
    if (tid < H_) { sm.eb[tid] = e_b[tid]; sm.gb[tid] = g_b[tid]; }
    if (tid < E_) { sm.eob[tid] = eo_b[tid]; }
    if (tid < H_ * QT) {
        ((float*)sm.m)[tid] = -1e30f;
        ((float*)sm.z)[tid] = 0.f;
    }
    __syncthreads();   // weights visible for hoisted fragment loads

    // hoisted loop-invariant GEMM-3 B fragments + eob pairs
    unsigned b3h[4][2], b3l[4][2];
    float eob0[4], eob1[4];
#pragma unroll
    for (int nt = 0; nt < 4; nt++) {
        b3h[nt][0] = __float_as_uint(sm.eowhi[nt * 8 + gid][ctg]);
        b3h[nt][1] = __float_as_uint(sm.eowhi[nt * 8 + gid][ctg + 4]);
        b3l[nt][0] = __float_as_uint(sm.eowlo[nt * 8 + gid][ctg]);
        b3l[nt][1] = __float_as_uint(sm.eowlo[nt * 8 + gid][ctg + 4]);
        eob0[nt] = sm.eob[nt * 8 + 2 * ctg];
        eob1[nt] = sm.eob[nt * 8 + 2 * ctg + 1];
    }

#pragma unroll
    for (int it = 0; it < 4; ++it) {
        int f4  = tid + it * 256;
        int row = f4 >> 6;
        int c   = (f4 & 63) * 4;
        *(float4*)&sm.q[row][c] =
            *(const float4*)&g_qkv[(bL + q0 + row) * (3 * D_) + c];
    }

    const unsigned ex_base = s2u(&sm.ex[0][0]);
    int ex_row[8], ex_col4[8], ex_chunk[8], ex_w4[8];
#pragma unroll
    for (int it = 0; it < 8; ++it) {
        int f4 = it * 256 + tid;
        int chunk  = f4 >> 7;
        int within = f4 & 127;
        int row    = chunk * 16 + (within >> 3);
        ex_chunk[it] = chunk;
        ex_w4[it]    = within;
        ex_row[it]   = row;
        ex_col4[it]  = (within & 7) ^ (row & 7);
    }

#pragma unroll
    for (int it = 0; it < 8; ++it)
        cp_async16(ex_base + ex_row[it] * 128 + ex_col4[it] * 16,
                   &edge_x[((bL + q0 + ex_chunk[it]) * L_ + 0) * E_ + ex_w4[it] * 4]);
#pragma unroll
    for (int it = 0; it < 4; ++it) {
        int f4  = tid + it * 256;
        int row = f4 >> 6;
        int c   = (f4 & 63) * 4;
        cp_async16(s2u(&sm.k[row][c]),
                   &g_qkv[(bL + row) * (3 * D_) + D_ + c]);
    }
    cp_commit();

    u64 acc2[QT];
#pragma unroll
    for (int i = 0; i < QT; i++) acc2[i] = 0ull;

    const u64 scl2 = dup2(SCALE_);

    for (int i = 0; i < NT; i++) {
        const int k0 = i * KT;

        cp_wait0();
        __syncthreads();

        u64 v2[KT / 2];
#pragma unroll
        for (int t2 = 0; t2 < KT / 2; t2++) {
            float a = g_qkv[(bL + k0 + 2 * t2 + 0) * (3 * D_) + 2 * D_ + w * HD_ + lane];
            float c = g_qkv[(bL + k0 + 2 * t2 + 1) * (3 * D_) + 2 * D_ + w * HD_ + lane];
            v2[t2] = pk2(a, c);
        }

        float ds[2][4];
#pragma unroll
        for (int nt = 0; nt < 2; nt++)
#pragma unroll
            for (int e = 0; e < 4; e++) ds[nt][e] = 0.f;
#pragma unroll
        for (int ks = 0; ks < 4; ks++) {
            const int qc = w * HD_ + ks * 8 + ctg;
            unsigned ah[4], al[4];
            tfsplit(sm.q[gid][qc],         ah[0], al[0]);
            tfsplit(sm.q[gid + 8][qc],     ah[1], al[1]);
            tfsplit(sm.q[gid][qc + 4],     ah[2], al[2]);
            tfsplit(sm.q[gid + 8][qc + 4], ah[3], al[3]);
#pragma unroll
            for (int nt = 0; nt < 2; nt++) {
                unsigned bh[2], bl[2];
                tfsplit(sm.k[nt * 8 + gid][qc],     bh[0], bl[0]);
                tfsplit(sm.k[nt * 8 + gid][qc + 4], bh[1], bl[1]);
                mma3x(ds[nt], ah, al, bh, bl);
            }
        }

#pragma unroll
        for (int mtl = 0; mtl < 2; mtl++) {
            const int mt = 2 * w + mtl;
            const int m0 = mt * 16;
            float d2[2][4];
#pragma unroll
            for (int nt = 0; nt < 2; nt++)
#pragma unroll
                for (int e = 0; e < 4; e++) d2[nt][e] = 0.f;
#pragma unroll
            for (int ks = 0; ks < 4; ks++) {
                const int c = ks * 8 + ctg;
                unsigned ah[4], al[4];
                tfsplit(((const float*)sm.ex)[ex_idx(m0 + gid,     c)],     ah[0], al[0]);
                tfsplit(((const float*)sm.ex)[ex_idx(m0 + gid + 8, c)],     ah[1], al[1]);
                tfsplit(((const float*)sm.ex)[ex_idx(m0 + gid,     c + 4)], ah[2], al[2]);
                tfsplit(((const float*)sm.ex)[ex_idx(m0 + gid + 8, c + 4)], ah[3], al[3]);
#pragma unroll
                for (int nt = 0; nt < 2; nt++) {
                    unsigned bh[2], bl[2];
                    bh[0] = __float_as_uint(sm.w2hi[nt * 8 + gid][c]);
                    bh[1] = __float_as_uint(sm.w2hi[nt * 8 + gid][c + 4]);
                    bl[0] = __float_as_uint(sm.w2lo[nt * 8 + gid][c]);
                    bl[1] = __float_as_uint(sm.w2lo[nt * 8 + gid][c + 4]);
                    mma3x(d2[nt], ah, al, bh, bl);
                }
            }
            const int h0 = 2 * ctg, h1 = 2 * ctg + 1;
            const int base0 = h0 * SROWH + mt * SROWQ;
            const int base1 = h1 * SROWH + mt * SROWQ;
            sm.s[base0 + gid]     = d2[0][0] + sm.eb[h0];
            sm.s[base1 + gid]     = d2[0][1] + sm.eb[h1];
            sm.s[base0 + gid + 8] = d2[0][2] + sm.eb[h0];
            sm.s[base1 + gid + 8] = d2[0][3] + sm.eb[h1];
            sm.g[base0 + gid]     = 1.f / (1.f + __expf(-(d2[1][0] + sm.gb[h0])));
            sm.g[base1 + gid]     = 1.f / (1.f + __expf(-(d2[1][1] + sm.gb[h1])));
            sm.g[base0 + gid + 8] = 1.f / (1.f + __expf(-(d2[1][2] + sm.gb[h0])));
            sm.g[base1 + gid + 8] = 1.f / (1.f + __expf(-(d2[1][3] + sm.gb[h1])));
        }
        __syncthreads();

#pragma unroll
        for (int nt = 0; nt < 2; nt++) {
            const int kc = nt * 8 + 2 * ctg;
            u64* p01 = (u64*)&sm.s[w * SROWH + gid * SROWQ + kc];
            u64* p23 = (u64*)&sm.s[w * SROWH + (gid + 8) * SROWQ + kc];
            *p01 = fma2(pk2(ds[nt][0], ds[nt][1]), scl2, *p01);
            *p23 = fma2(pk2(ds[nt][2], ds[nt][3]), scl2, *p23);
        }
        __syncthreads();

#pragma unroll
        for (int mtl = 0; mtl < 2; mtl++) {
            const int mt = 2 * w + mtl;
            unsigned ah[4], al[4];
            tfsplit(sm.s[ctg * SROWH + mt * SROWQ + gid],           ah[0], al[0]);
            tfsplit(sm.s[ctg * SROWH + mt * SROWQ + gid + 8],       ah[1], al[1]);
            tfsplit(sm.s[(ctg + 4) * SROWH + mt * SROWQ + gid],     ah[2], al[2]);
            tfsplit(sm.s[(ctg + 4) * SROWH + mt * SROWQ + gid + 8], ah[3], al[3]);
            float d3[4][4];
#pragma unroll
            for (int nt = 0; nt < 4; nt++) {
#pragma unroll
                for (int e = 0; e < 4; e++) d3[nt][e] = 0.f;
                mma3x(d3[nt], ah, al, b3h[nt], b3l[nt]);
            }
#pragma unroll
            for (int nt = 0; nt < 4; nt++) {
                const int col = nt * 8 + 2 * ctg;
                const int row = mt * 16 + gid;
                float o0 = d3[nt][0] + eob0[nt];
                float o1 = d3[nt][1] + eob1[nt];
                float o2 = d3[nt][2] + eob0[nt];
                float o3 = d3[nt][3] + eob1[nt];
                *(u64*)&((float*)sm.ex)[ex_idx(row, col)]     = pk2(o0, o1);
                *(u64*)&((float*)sm.ex)[ex_idx(row + 8, col)] = pk2(o2, o3);
            }
        }
        __syncthreads();

#pragma unroll
        for (int it = 0; it < 8; ++it) {
            float4 v4 = *(const float4*)&((const float*)sm.ex)
                            [ex_row[it] * 32 + ex_col4[it] * 4];
            *(float4*)&edge_out[((bL + q0 + ex_chunk[it]) * L_ + k0) * E_
                                + ex_w4[it] * 4] = v4;
        }

        if (i + 1 < NT) {
#pragma unroll
            for (int it = 0; it < 8; ++it)
                cp_async16(ex_base + ex_row[it] * 128 + ex_col4[it] * 16,
                           &edge_x[((bL + q0 + ex_chunk[it]) * L_ + k0 + KT) * E_
                                   + ex_w4[it] * 4]);
#pragma unroll
            for (int it = 0; it < 4; ++it) {
                int f4  = tid + it * 256;
                int row = f4 >> 6;
                int c   = (f4 & 63) * 4;
                cp_async16(s2u(&sm.k[row][c]),
                           &g_qkv[(bL + k0 + KT + row) * (3 * D_) + D_ + c]);
            }
        }
        cp_commit();

        if (lane < QT) {
            const int q = lane;
            float* srow = &sm.s[w * SROWH + q * SROWQ];
            float* grow = &sm.g[w * SROWH + q * SROWQ];
            float mold = sm.m[w][q];
            float tmax = -1e30f;
#pragma unroll
            for (int t4 = 0; t4 < 4; t4++) {
                float4 sv = *(const float4*)&srow[t4 * 4];
                tmax = fmaxf(tmax, fmaxf(fmaxf(sv.x, sv.y), fmaxf(sv.z, sv.w)));
            }
            float mnew = fmaxf(mold, tmax);
            float r    = __expf(mold - mnew);
            float zs   = 0.f;
#pragma unroll
            for (int t4 = 0; t4 < 4; t4++) {
                float4 sv = *(const float4*)&srow[t4 * 4];
                float4 gv = *(const float4*)&grow[t4 * 4];
                float p0 = __expf(sv.x - mnew);
                float p1 = __expf(sv.y - mnew);
                float p2 = __expf(sv.z - mnew);
                float p3 = __expf(sv.w - mnew);
                zs += (p0 + p1) + (p2 + p3);
                float4 o;
                o.x = p0 * gv.x; o.y = p1 * gv.y; o.z = p2 * gv.z; o.w = p3 * gv.w;
                *(float4*)&srow[t4 * 4] = o;
            }
            sm.z[w][q] = sm.z[w][q] * r + zs;
            sm.m[w][q] = mnew;
            sm.r[w][q] = r;
        }
        __syncwarp();
#pragma unroll
        for (int q = 0; q < QT; q++) {
            u64 a2 = mul2(acc2[q], dup2(sm.r[w][q]));
            const u64* prow = (const u64*)&sm.s[w * SROWH + q * SROWQ];
#pragma unroll
            for (int j = 0; j < 4; ++j) {
                a2 = fma2(prow[2 * j],     v2[2 * j],     a2);
                a2 = fma2(prow[2 * j + 1], v2[2 * j + 1], a2);
            }
            acc2[q] = a2;
        }
    }

#pragma unroll
    for (int q = 0; q < QT; q++) {
        g_aout[(bL + q0 + q) * D_ + w * HD_ + lane] = hsum2(acc2[q]) / sm.z[w][q];
    }
}

// ---------------------------------------------------------------------------
// kernel_launch
// ---------------------------------------------------------------------------
extern "C" void kernel_launch(void* const* d_in, const int* in_sizes, int n_in,
                              void* d_out, int out_size)
{
    const float* x       = (const float*)d_in[0];
    const float* edge_x  = (const float*)d_in[1];
    const float* in_w    = (const float*)d_in[2];
    const float* in_b    = (const float*)d_in[3];
    const float* out_w   = (const float*)d_in[4];
    const float* out_b   = (const float*)d_in[5];
    const float* e_w     = (const float*)d_in[6];
    const float* e_b     = (const float*)d_in[7];
    const float* g_w     = (const float*)d_in[8];
    const float* g_b     = (const float*)d_in[9];
    const float* eo_w    = (const float*)d_in[10];
    const float* eo_b    = (const float*)d_in[11];

    float* out0     = (float*)d_out;
    float* edge_out = out0 + (size_t)B_ * L_ * D_;

    float* qkv_ptr  = nullptr;
    float* aout_ptr = nullptr;
    cudaGetSymbolAddress((void**)&qkv_ptr,  g_qkv);
    cudaGetSymbolAddress((void**)&aout_ptr, g_aout);

    const int attn_smem = (int)sizeof(AttnSmem);
    const int gemm_smem = (int)sizeof(GemmSmem);
    cudaFuncSetAttribute(edge_attn_kernel,
                         cudaFuncAttributeMaxDynamicSharedMemorySize, attn_smem);
    cudaFuncSetAttribute(tf32_gemm_nt_bias,
                         cudaFuncAttributeMaxDynamicSharedMemorySize, gemm_smem);

    // 1) qkv = x @ in_proj_w^T + b
    tf32_gemm_nt_bias<<<dim3(3 * D_ / GBN, ROWS_ / GBM), 256, gemm_smem>>>(
        x, in_w, in_b, qkv_ptr, ROWS_, 3 * D_, D_);

    // 2) fused edge attention
    edge_attn_kernel<<<dim3(L_ / QT, B_), 256, attn_smem>>>(
        edge_x, e_w, e_b, g_w, g_b, eo_w, eo_b, edge_out);

    // 3) out = aout @ out_w^T + out_b
    tf32_gemm_nt_bias<<<dim3(D_ / GBN, ROWS_ / GBM), 256, gemm_smem>>>(
        aout_ptr, out_w, out_b, out0, ROWS_, D_, D_);
}

// round 9
// speedup vs baseline: 1.0828x; 1.0828x over previous
#include <cuda_runtime.h>
#include <math.h>

// ---------------------------------------------------------------------------
// Problem constants
// ---------------------------------------------------------------------------
constexpr int B_  = 32;
constexpr int L_  = 256;
constexpr int D_  = 256;
constexpr int E_  = 32;
constexpr int H_  = 8;
constexpr int HD_ = 32;
constexpr float SCALE_ = 0.17677669529663687f;  // 1/sqrt(32)

constexpr int ROWS_ = B_ * L_;   // 8192

// ---------------------------------------------------------------------------
// Device scratch
// ---------------------------------------------------------------------------
__device__ float g_qkv[ROWS_ * 3 * D_];   // [B*L, 768]  q|k|v
__device__ float g_aout[ROWS_ * D_];      // [B*L, 256]

// ---------------------------------------------------------------------------
// helpers
// ---------------------------------------------------------------------------
using u64 = unsigned long long;

__device__ __forceinline__ unsigned s2u(const void* p) {
    return (unsigned)__cvta_generic_to_shared(p);
}
__device__ __forceinline__ u64 fma2(u64 a, u64 b, u64 c) {
    u64 d; asm("fma.rn.f32x2 %0, %1, %2, %3;" : "=l"(d) : "l"(a), "l"(b), "l"(c));
    return d;
}
__device__ __forceinline__ u64 mul2(u64 a, u64 b) {
    u64 d; asm("mul.rn.f32x2 %0, %1, %2;" : "=l"(d) : "l"(a), "l"(b));
    return d;
}
__device__ __forceinline__ float hsum2(u64 a) {
    float lo, hi;
    asm("mov.b64 {%0,%1}, %2;" : "=f"(lo), "=f"(hi) : "l"(a));
    return lo + hi;
}
__device__ __forceinline__ u64 dup2(float x) {
    u64 d; asm("mov.b64 %0, {%1,%1};" : "=l"(d) : "f"(x)); return d;
}
__device__ __forceinline__ u64 pk2(float x, float y) {
    u64 d; asm("mov.b64 %0, {%1,%2};" : "=l"(d) : "f"(x), "f"(y)); return d;
}
__device__ __forceinline__ void cp_async16(unsigned smem_dst, const void* gmem_src) {
    asm volatile("cp.async.cg.shared.global [%0], [%1], 16;\n"
                 :: "r"(smem_dst), "l"(gmem_src) : "memory");
}
__device__ __forceinline__ void cp_commit() {
    asm volatile("cp.async.commit_group;\n" ::: "memory");
}
__device__ __forceinline__ void cp_wait0() {
    asm volatile("cp.async.wait_group 0;\n" ::: "memory");
}
// tf32 conversion + split (3xTF32)
__device__ __forceinline__ unsigned f2tf(float x) {
    unsigned r; asm("cvt.rna.tf32.f32 %0, %1;" : "=r"(r) : "f"(x)); return r;
}
__device__ __forceinline__ void tfsplit(float x, unsigned& hi, unsigned& lo) {
    hi = f2tf(x);
    lo = f2tf(x - __uint_as_float(hi));
}
// m16n8k8 tf32 MMA, D += A*B
__device__ __forceinline__ void mma8(float* d, const unsigned* a, const unsigned* b) {
    asm volatile(
        "mma.sync.aligned.m16n8k8.row.col.f32.tf32.tf32.f32 "
        "{%0,%1,%2,%3},{%4,%5,%6,%7},{%8,%9},{%0,%1,%2,%3};"
        : "+f"(d[0]), "+f"(d[1]), "+f"(d[2]), "+f"(d[3])
        : "r"(a[0]), "r"(a[1]), "r"(a[2]), "r"(a[3]), "r"(b[0]), "r"(b[1]));
}
__device__ __forceinline__ void mma3x(float* d, const unsigned* ah, const unsigned* al,
                                      const unsigned* bh, const unsigned* bl) {
    mma8(d, ah, bh);
    mma8(d, ah, bl);
    mma8(d, al, bh);
}

// ---------------------------------------------------------------------------
// Kernel 1/3: tf32 tensor-core GEMM, C = A @ W^T + bias (3xTF32)
// Pre-split hi/lo planes in smem; register prefetch of next tile.  (r8, kept)
// ---------------------------------------------------------------------------
constexpr int GBM = 128;
constexpr int GBN = 64;
constexpr int GBK = 32;
constexpr int GSTR = GBK + 4;    // 36

struct GemmSmem {
    float Ah[GBM][GSTR];
    float Al[GBM][GSTR];
    float Wh[GBN][GSTR];
    float Wl[GBN][GSTR];
};

__global__ __launch_bounds__(256, 2)
void tf32_gemm_nt_bias(const float* __restrict__ A, const float* __restrict__ W,
                       const float* __restrict__ bias, float* __restrict__ C,
                       int M, int N, int K)
{
    extern __shared__ char smem_raw[];
    GemmSmem& sm = *reinterpret_cast<GemmSmem*>(smem_raw);

    const int tid  = threadIdx.x;
    const int w    = tid >> 5;
    const int lane = tid & 31;
    const int gid  = lane >> 2;
    const int ctg  = lane & 3;
    const int wm   = w >> 1;
    const int wn   = w & 1;
    const int m0   = blockIdx.y * GBM;
    const int n0   = blockIdx.x * GBN;

    const int NIT = K / GBK;

    int arow[4], ac4[4], wrow[2], wc4[2];
#pragma unroll
    for (int it = 0; it < 4; ++it) {
        int idx = tid + it * 256;
        arow[it] = idx >> 3;
        ac4[it]  = (idx & 7) * 4;
    }
#pragma unroll
    for (int it = 0; it < 2; ++it) {
        int idx = tid + it * 256;
        wrow[it] = idx >> 3;
        wc4[it]  = (idx & 7) * 4;
    }

    float4 ar[4], wr[2];
#pragma unroll
    for (int it = 0; it < 4; ++it)
        ar[it] = *(const float4*)&A[(size_t)(m0 + arow[it]) * K + ac4[it]];
#pragma unroll
    for (int it = 0; it < 2; ++it)
        wr[it] = *(const float4*)&W[(size_t)(n0 + wrow[it]) * K + wc4[it]];

    float acc[2][4][4];
#pragma unroll
    for (int mt = 0; mt < 2; mt++)
#pragma unroll
        for (int nt = 0; nt < 4; nt++)
#pragma unroll
            for (int e = 0; e < 4; e++) acc[mt][nt][e] = 0.f;

    for (int i = 0; i < NIT; i++) {
        __syncthreads();

#pragma unroll
        for (int it = 0; it < 4; ++it) {
            unsigned h0,l0,h1,l1,h2,l2,h3,l3;
            tfsplit(ar[it].x, h0, l0); tfsplit(ar[it].y, h1, l1);
            tfsplit(ar[it].z, h2, l2); tfsplit(ar[it].w, h3, l3);
            float4 hv = make_float4(__uint_as_float(h0), __uint_as_float(h1),
                                    __uint_as_float(h2), __uint_as_float(h3));
            float4 lv = make_float4(__uint_as_float(l0), __uint_as_float(l1),
                                    __uint_as_float(l2), __uint_as_float(l3));
            *(float4*)&sm.Ah[arow[it]][ac4[it]] = hv;
            *(float4*)&sm.Al[arow[it]][ac4[it]] = lv;
        }
#pragma unroll
        for (int it = 0; it < 2; ++it) {
            unsigned h0,l0,h1,l1,h2,l2,h3,l3;
            tfsplit(wr[it].x, h0, l0); tfsplit(wr[it].y, h1, l1);
            tfsplit(wr[it].z, h2, l2); tfsplit(wr[it].w, h3, l3);
            float4 hv = make_float4(__uint_as_float(h0), __uint_as_float(h1),
                                    __uint_as_float(h2), __uint_as_float(h3));
            float4 lv = make_float4(__uint_as_float(l0), __uint_as_float(l1),
                                    __uint_as_float(l2), __uint_as_float(l3));
            *(float4*)&sm.Wh[wrow[it]][wc4[it]] = hv;
            *(float4*)&sm.Wl[wrow[it]][wc4[it]] = lv;
        }
        __syncthreads();

        if (i + 1 < NIT) {
            const int k0 = (i + 1) * GBK;
#pragma unroll
            for (int it = 0; it < 4; ++it)
                ar[it] = *(const float4*)&A[(size_t)(m0 + arow[it]) * K + k0 + ac4[it]];
#pragma unroll
            for (int it = 0; it < 2; ++it)
                wr[it] = *(const float4*)&W[(size_t)(n0 + wrow[it]) * K + k0 + wc4[it]];
        }

#pragma unroll
        for (int ks = 0; ks < 4; ks++) {
            const int kc = ks * 8 + ctg;
            unsigned ah[2][4], al[2][4];
#pragma unroll
            for (int mt = 0; mt < 2; mt++) {
                const int r0 = wm * 32 + mt * 16 + gid;
                ah[mt][0] = __float_as_uint(sm.Ah[r0][kc]);
                ah[mt][1] = __float_as_uint(sm.Ah[r0 + 8][kc]);
                ah[mt][2] = __float_as_uint(sm.Ah[r0][kc + 4]);
                ah[mt][3] = __float_as_uint(sm.Ah[r0 + 8][kc + 4]);
                al[mt][0] = __float_as_uint(sm.Al[r0][kc]);
                al[mt][1] = __float_as_uint(sm.Al[r0 + 8][kc]);
                al[mt][2] = __float_as_uint(sm.Al[r0][kc + 4]);
                al[mt][3] = __float_as_uint(sm.Al[r0 + 8][kc + 4]);
            }
#pragma unroll
            for (int nt = 0; nt < 4; nt++) {
                const int nr = wn * 32 + nt * 8 + gid;
                unsigned bh[2], bl[2];
                bh[0] = __float_as_uint(sm.Wh[nr][kc]);
                bh[1] = __float_as_uint(sm.Wh[nr][kc + 4]);
                bl[0] = __float_as_uint(sm.Wl[nr][kc]);
                bl[1] = __float_as_uint(sm.Wl[nr][kc + 4]);
                mma3x(acc[0][nt], ah[0], al[0], bh, bl);
                mma3x(acc[1][nt], ah[1], al[1], bh, bl);
            }
        }
    }

#pragma unroll
    for (int mt = 0; mt < 2; mt++) {
        const int row = m0 + wm * 32 + mt * 16 + gid;
#pragma unroll
        for (int nt = 0; nt < 4; nt++) {
            const int col = n0 + wn * 32 + nt * 8 + 2 * ctg;
            const float b0 = bias[col], b1 = bias[col + 1];
            *(u64*)&C[(size_t)row * N + col] =
                pk2(acc[mt][nt][0] + b0, acc[mt][nt][1] + b1);
            *(u64*)&C[(size_t)(row + 8) * N + col] =
                pk2(acc[mt][nt][2] + b0, acc[mt][nt][3] + b1);
        }
    }
}

// ---------------------------------------------------------------------------
// Kernel 2: fused edge attention (v8 — q pre-split planes, tiered GEMM-2)
// ---------------------------------------------------------------------------
constexpr int QT = 16;
constexpr int KT = 16;
constexpr int NT = L_ / KT;
constexpr int QSTR  = D_ + 4;          // 260
constexpr int SROWQ = 20;
constexpr int SROWH = QT * SROWQ + 4;  // 324

struct AttnSmem {
    float qhi[QT][QSTR];          // q tf32-hi plane (pre-split, loop-invariant)
    float qlo[QT][QSTR];          // q residual plane
    float k[KT][QSTR];
    float ex[QT * KT][E_];        // XOR-swizzled at float4 granularity
    float s[H_ * SROWH];
    float g[H_ * SROWH];
    float m[H_][QT];
    float z[H_][QT];
    float r[H_][QT];
    float w2hi[16][36];
    float w2lo[16][36];
    float eowhi[E_][9];
    float eowlo[E_][9];
    float eb[H_];
    float gb[H_];
    float eob[E_];
};

__device__ __forceinline__ int ex_idx(int row, int col) {
    return row * 32 + (((col >> 2) ^ (row & 7)) << 2) + (col & 3);
}

__global__ __launch_bounds__(256, 2)
void edge_attn_kernel(const float* __restrict__ edge_x,
                      const float* __restrict__ e_w, const float* __restrict__ e_b,
                      const float* __restrict__ g_w, const float* __restrict__ g_b,
                      const float* __restrict__ eo_w, const float* __restrict__ eo_b,
                      float* __restrict__ edge_out)
{
    extern __shared__ char smem_raw[];
    AttnSmem& sm = *reinterpret_cast<AttnSmem*>(smem_raw);

    const int tid = threadIdx.x;
    const int b   = blockIdx.y;
    const int q0  = blockIdx.x * QT;
    const size_t bL = (size_t)b * L_;

    const int w    = tid >> 5;
    const int lane = tid & 31;
    const int gid  = lane >> 2;
    const int ctg  = lane & 3;

#pragma unroll
    for (int it = 0; it < 2; ++it) {
        int idx = tid + it * 256;
        int rr = idx >> 5, cc = idx & 31;
        float val = (rr < 8) ? e_w[rr * E_ + cc] : g_w[(rr - 8) * E_ + cc];
        unsigned hi, lo; tfsplit(val, hi, lo);
        sm.w2hi[rr][cc] = __uint_as_float(hi);
        sm.w2lo[rr][cc] = __uint_as_float(lo);
    }
    {
        int n = tid >> 3, hc = tid & 7;
        unsigned hi, lo; tfsplit(eo_w[n * H_ + hc], hi, lo);
        sm.eowhi[n][hc] = __uint_as_float(hi);
        sm.eowlo[n][hc] = __uint_as_float(lo);
    }
    if (tid < H_) { sm.eb[tid] = e_b[tid]; sm.gb[tid] = g_b[tid]; }
    if (tid < E_) { sm.eob[tid] = eo_b[tid]; }
    if (tid < H_ * QT) {
        ((float*)sm.m)[tid] = -1e30f;
        ((float*)sm.z)[tid] = 0.f;
    }

    // --- q tile: load, split once, store hi/lo planes ---
#pragma unroll
    for (int it = 0; it < 4; ++it) {
        int f4  = tid + it * 256;
        int row = f4 >> 6;
        int c   = (f4 & 63) * 4;
        float4 v = *(const float4*)&g_qkv[(bL + q0 + row) * (3 * D_) + c];
        unsigned h0,l0,h1,l1,h2,l2,h3,l3;
        tfsplit(v.x, h0, l0); tfsplit(v.y, h1, l1);
        tfsplit(v.z, h2, l2); tfsplit(v.w, h3, l3);
        *(float4*)&sm.qhi[row][c] = make_float4(
            __uint_as_float(h0), __uint_as_float(h1),
            __uint_as_float(h2), __uint_as_float(h3));
        *(float4*)&sm.qlo[row][c] = make_float4(
            __uint_as_float(l0), __uint_as_float(l1),
            __uint_as_float(l2), __uint_as_float(l3));
    }

    const unsigned ex_base = s2u(&sm.ex[0][0]);
    int ex_row[8], ex_col4[8], ex_chunk[8], ex_w4[8];
#pragma unroll
    for (int it = 0; it < 8; ++it) {
        int f4 = it * 256 + tid;
        int chunk  = f4 >> 7;
        int within = f4 & 127;
        int row    = chunk * 16 + (within >> 3);
        ex_chunk[it] = chunk;
        ex_w4[it]    = within;
        ex_row[it]   = row;
        ex_col4[it]  = (within & 7) ^ (row & 7);
    }

#pragma unroll
    for (int it = 0; it < 8; ++it)
        cp_async16(ex_base + ex_row[it] * 128 + ex_col4[it] * 16,
                   &edge_x[((bL + q0 + ex_chunk[it]) * L_ + 0) * E_ + ex_w4[it] * 4]);
#pragma unroll
    for (int it = 0; it < 4; ++it) {
        int f4  = tid + it * 256;
        int row = f4 >> 6;
        int c   = (f4 & 63) * 4;
        cp_async16(s2u(&sm.k[row][c]),
                   &g_qkv[(bL + row) * (3 * D_) + D_ + c]);
    }
    cp_commit();

    u64 acc2[QT];
#pragma unroll
    for (int i = 0; i < QT; i++) acc2[i] = 0ull;

    const u64 scl2 = dup2(SCALE_);

    for (int i = 0; i < NT; i++) {
        const int k0 = i * KT;

        cp_wait0();
        __syncthreads();

        u64 v2[KT / 2];
#pragma unroll
        for (int t2 = 0; t2 < KT / 2; t2++) {
            float a = g_qkv[(bL + k0 + 2 * t2 + 0) * (3 * D_) + 2 * D_ + w * HD_ + lane];
            float c = g_qkv[(bL + k0 + 2 * t2 + 1) * (3 * D_) + 2 * D_ + w * HD_ + lane];
            v2[t2] = pk2(a, c);
        }

        // ===== scores MMA (full 3xTF32; q planes pre-split) =====
        float ds[2][4];
#pragma unroll
        for (int nt = 0; nt < 2; nt++)
#pragma unroll
            for (int e = 0; e < 4; e++) ds[nt][e] = 0.f;
#pragma unroll
        for (int ks = 0; ks < 4; ks++) {
            const int qc = w * HD_ + ks * 8 + ctg;
            unsigned ah[4], al[4];
            ah[0] = __float_as_uint(sm.qhi[gid][qc]);
            ah[1] = __float_as_uint(sm.qhi[gid + 8][qc]);
            ah[2] = __float_as_uint(sm.qhi[gid][qc + 4]);
            ah[3] = __float_as_uint(sm.qhi[gid + 8][qc + 4]);
            al[0] = __float_as_uint(sm.qlo[gid][qc]);
            al[1] = __float_as_uint(sm.qlo[gid + 8][qc]);
            al[2] = __float_as_uint(sm.qlo[gid][qc + 4]);
            al[3] = __float_as_uint(sm.qlo[gid + 8][qc + 4]);
#pragma unroll
            for (int nt = 0; nt < 2; nt++) {
                unsigned bh[2], bl[2];
                tfsplit(sm.k[nt * 8 + gid][qc],     bh[0], bl[0]);
                tfsplit(sm.k[nt * 8 + gid][qc + 4], bh[1], bl[1]);
                mma3x(ds[nt], ah, al, bh, bl);
            }
        }

        // ===== GEMM-2: e/g projection (tiered: e=2 MMA, g=1 MMA; no A-lo) =====
#pragma unroll
        for (int mtl = 0; mtl < 2; mtl++) {
            const int mt = 2 * w + mtl;
            const int m0 = mt * 16;
            float d2[2][4];
#pragma unroll
            for (int nt = 0; nt < 2; nt++)
#pragma unroll
                for (int e = 0; e < 4; e++) d2[nt][e] = 0.f;
#pragma unroll
            for (int ks = 0; ks < 4; ks++) {
                const int c = ks * 8 + ctg;
                unsigned ah[4];
                ah[0] = f2tf(((const float*)sm.ex)[ex_idx(m0 + gid,     c)]);
                ah[1] = f2tf(((const float*)sm.ex)[ex_idx(m0 + gid + 8, c)]);
                ah[2] = f2tf(((const float*)sm.ex)[ex_idx(m0 + gid,     c + 4)]);
                ah[3] = f2tf(((const float*)sm.ex)[ex_idx(m0 + gid + 8, c + 4)]);
                // e (rows 0..7 of w2): hi + A·B-lo compensation
                {
                    unsigned bh[2], bl[2];
                    bh[0] = __float_as_uint(sm.w2hi[gid][c]);
                    bh[1] = __float_as_uint(sm.w2hi[gid][c + 4]);
                    bl[0] = __float_as_uint(sm.w2lo[gid][c]);
                    bl[1] = __float_as_uint(sm.w2lo[gid][c + 4]);
                    mma8(d2[0], ah, bh);
                    mma8(d2[0], ah, bl);
                }
                // gate (rows 8..15): hi only (sigmoid is error-tolerant)
                {
                    unsigned bh[2];
                    bh[0] = __float_as_uint(sm.w2hi[8 + gid][c]);
                    bh[1] = __float_as_uint(sm.w2hi[8 + gid][c + 4]);
                    mma8(d2[1], ah, bh);
                }
            }
            const int h0 = 2 * ctg, h1 = 2 * ctg + 1;
            const int base0 = h0 * SROWH + mt * SROWQ;
            const int base1 = h1 * SROWH + mt * SROWQ;
            sm.s[base0 + gid]     = d2[0][0] + sm.eb[h0];
            sm.s[base1 + gid]     = d2[0][1] + sm.eb[h1];
            sm.s[base0 + gid + 8] = d2[0][2] + sm.eb[h0];
            sm.s[base1 + gid + 8] = d2[0][3] + sm.eb[h1];
            sm.g[base0 + gid]     = 1.f / (1.f + __expf(-(d2[1][0] + sm.gb[h0])));
            sm.g[base1 + gid]     = 1.f / (1.f + __expf(-(d2[1][1] + sm.gb[h1])));
            sm.g[base0 + gid + 8] = 1.f / (1.f + __expf(-(d2[1][2] + sm.gb[h0])));
            sm.g[base1 + gid + 8] = 1.f / (1.f + __expf(-(d2[1][3] + sm.gb[h1])));
        }
        __syncthreads();

#pragma unroll
        for (int nt = 0; nt < 2; nt++) {
            const int kc = nt * 8 + 2 * ctg;
            u64* p01 = (u64*)&sm.s[w * SROWH + gid * SROWQ + kc];
            u64* p23 = (u64*)&sm.s[w * SROWH + (gid + 8) * SROWQ + kc];
            *p01 = fma2(pk2(ds[nt][0], ds[nt][1]), scl2, *p01);
            *p23 = fma2(pk2(ds[nt][2], ds[nt][3]), scl2, *p23);
        }
        __syncthreads();

        // ===== GEMM-3: edge_out (full 3xTF32) =====
#pragma unroll
        for (int mtl = 0; mtl < 2; mtl++) {
            const int mt = 2 * w + mtl;
            unsigned ah[4], al[4];
            tfsplit(sm.s[ctg * SROWH + mt * SROWQ + gid],           ah[0], al[0]);
            tfsplit(sm.s[ctg * SROWH + mt * SROWQ + gid + 8],       ah[1], al[1]);
            tfsplit(sm.s[(ctg + 4) * SROWH + mt * SROWQ + gid],     ah[2], al[2]);
            tfsplit(sm.s[(ctg + 4) * SROWH + mt * SROWQ + gid + 8], ah[3], al[3]);
            float d3[4][4];
#pragma unroll
            for (int nt = 0; nt < 4; nt++) {
                unsigned bh[2], bl[2];
                bh[0] = __float_as_uint(sm.eowhi[nt * 8 + gid][ctg]);
                bh[1] = __float_as_uint(sm.eowhi[nt * 8 + gid][ctg + 4]);
                bl[0] = __float_as_uint(sm.eowlo[nt * 8 + gid][ctg]);
                bl[1] = __float_as_uint(sm.eowlo[nt * 8 + gid][ctg + 4]);
#pragma unroll
                for (int e = 0; e < 4; e++) d3[nt][e] = 0.f;
                mma3x(d3[nt], ah, al, bh, bl);
            }
#pragma unroll
            for (int nt = 0; nt < 4; nt++) {
                const int col = nt * 8 + 2 * ctg;
                const int row = mt * 16 + gid;
                float o0 = d3[nt][0] + sm.eob[col];
                float o1 = d3[nt][1] + sm.eob[col + 1];
                float o2 = d3[nt][2] + sm.eob[col];
                float o3 = d3[nt][3] + sm.eob[col + 1];
                *(u64*)&((float*)sm.ex)[ex_idx(row, col)]     = pk2(o0, o1);
                *(u64*)&((float*)sm.ex)[ex_idx(row + 8, col)] = pk2(o2, o3);
            }
        }
        __syncthreads();

#pragma unroll
        for (int it = 0; it < 8; ++it) {
            float4 v4 = *(const float4*)&((const float*)sm.ex)
                            [ex_row[it] * 32 + ex_col4[it] * 4];
            *(float4*)&edge_out[((bL + q0 + ex_chunk[it]) * L_ + k0) * E_
                                + ex_w4[it] * 4] = v4;
        }

        if (i + 1 < NT) {
#pragma unroll
            for (int it = 0; it < 8; ++it)
                cp_async16(ex_base + ex_row[it] * 128 + ex_col4[it] * 16,
                           &edge_x[((bL + q0 + ex_chunk[it]) * L_ + k0 + KT) * E_
                                   + ex_w4[it] * 4]);
#pragma unroll
            for (int it = 0; it < 4; ++it) {
                int f4  = tid + it * 256;
                int row = f4 >> 6;
                int c   = (f4 & 63) * 4;
                cp_async16(s2u(&sm.k[row][c]),
                           &g_qkv[(bL + k0 + KT + row) * (3 * D_) + D_ + c]);
            }
        }
        cp_commit();

        if (lane < QT) {
            const int q = lane;
            float* srow = &sm.s[w * SROWH + q * SROWQ];
            float* grow = &sm.g[w * SROWH + q * SROWQ];
            float mold = sm.m[w][q];
            float tmax = -1e30f;
#pragma unroll
            for (int t4 = 0; t4 < 4; t4++) {
                float4 sv = *(const float4*)&srow[t4 * 4];
                tmax = fmaxf(tmax, fmaxf(fmaxf(sv.x, sv.y), fmaxf(sv.z, sv.w)));
            }
            float mnew = fmaxf(mold, tmax);
            float r    = __expf(mold - mnew);
            float zs   = 0.f;
#pragma unroll
            for (int t4 = 0; t4 < 4; t4++) {
                float4 sv = *(const float4*)&srow[t4 * 4];
                float4 gv = *(const float4*)&grow[t4 * 4];
                float p0 = __expf(sv.x - mnew);
                float p1 = __expf(sv.y - mnew);
                float p2 = __expf(sv.z - mnew);
                float p3 = __expf(sv.w - mnew);
                zs += (p0 + p1) + (p2 + p3);
                float4 o;
                o.x = p0 * gv.x; o.y = p1 * gv.y; o.z = p2 * gv.z; o.w = p3 * gv.w;
                *(float4*)&srow[t4 * 4] = o;
            }
            sm.z[w][q] = sm.z[w][q] * r + zs;
            sm.m[w][q] = mnew;
            sm.r[w][q] = r;
        }
        __syncwarp();
#pragma unroll
        for (int q = 0; q < QT; q++) {
            u64 a2 = mul2(acc2[q], dup2(sm.r[w][q]));
            const u64* prow = (const u64*)&sm.s[w * SROWH + q * SROWQ];
#pragma unroll
            for (int j = 0; j < 4; ++j) {
                a2 = fma2(prow[2 * j],     v2[2 * j],     a2);
                a2 = fma2(prow[2 * j + 1], v2[2 * j + 1], a2);
            }
            acc2[q] = a2;
        }
    }

#pragma unroll
    for (int q = 0; q < QT; q++) {
        g_aout[(bL + q0 + q) * D_ + w * HD_ + lane] = hsum2(acc2[q]) / sm.z[w][q];
    }
}

// ---------------------------------------------------------------------------
// kernel_launch
// ---------------------------------------------------------------------------
extern "C" void kernel_launch(void* const* d_in, const int* in_sizes, int n_in,
                              void* d_out, int out_size)
{
    const float* x       = (const float*)d_in[0];
    const float* edge_x  = (const float*)d_in[1];
    const float* in_w    = (const float*)d_in[2];
    const float* in_b    = (const float*)d_in[3];
    const float* out_w   = (const float*)d_in[4];
    const float* out_b   = (const float*)d_in[5];
    const float* e_w     = (const float*)d_in[6];
    const float* e_b     = (const float*)d_in[7];
    const float* g_w     = (const float*)d_in[8];
    const float* g_b     = (const float*)d_in[9];
    const float* eo_w    = (const float*)d_in[10];
    const float* eo_b    = (const float*)d_in[11];

    float* out0     = (float*)d_out;
    float* edge_out = out0 + (size_t)B_ * L_ * D_;

    float* qkv_ptr  = nullptr;
    float* aout_ptr = nullptr;
    cudaGetSymbolAddress((void**)&qkv_ptr,  g_qkv);
    cudaGetSymbolAddress((void**)&aout_ptr, g_aout);

    const int attn_smem = (int)sizeof(AttnSmem);
    const int gemm_smem = (int)sizeof(GemmSmem);
    cudaFuncSetAttribute(edge_attn_kernel,
                         cudaFuncAttributeMaxDynamicSharedMemorySize, attn_smem);
    cudaFuncSetAttribute(tf32_gemm_nt_bias,
                         cudaFuncAttributeMaxDynamicSharedMemorySize, gemm_smem);

    // 1) qkv = x @ in_proj_w^T + b
    tf32_gemm_nt_bias<<<dim3(3 * D_ / GBN, ROWS_ / GBM), 256, gemm_smem>>>(
        x, in_w, in_b, qkv_ptr, ROWS_, 3 * D_, D_);

    // 2) fused edge attention
    edge_attn_kernel<<<dim3(L_ / QT, B_), 256, attn_smem>>>(
        edge_x, e_w, e_b, g_w, g_b, eo_w, eo_b, edge_out);

    // 3) out = aout @ out_w^T + out_b
    tf32_gemm_nt_bias<<<dim3(D_ / GBN, ROWS_ / GBM), 256, gemm_smem>>>(
        aout_ptr, out_w, out_b, out0, ROWS_, D_, D_);
}